// round 1
// baseline (speedup 1.0000x reference)
#include <cuda_runtime.h>
#include <cuda_bf16.h>
#include <cstdio>

#define BATCH 16
#define LEN   128
#define HID   128
#define G4    512   // 4*HID
#define EMB   128
#define D2    256   // 2*HID

// ---------------- scratch (device globals; no allocation) ----------------
__device__ float  g_x  [BATCH*LEN*EMB];        // embedded input
__device__ float  g_xp [2*BATCH*LEN*G4];       // input projections (per layer, reused)
__device__ float  g_h0 [BATCH*LEN*D2];         // layer0 bilstm out
__device__ float  g_h1 [BATCH*LEN*D2];         // layer1 bilstm out
__device__ float4 g_whh[2*2*32*G4];            // packed w_hh: [layer][dir][k4][gate] float4 over k
__device__ float  g_a  [BATCH*LEN*100];
__device__ float  g_bp [BATCH*LEN*100];

// ---------------- helpers ----------------
__device__ __forceinline__ float sigf(float x){
    float e = __expf(-x);
    return __fdividef(1.f, 1.f + e);
}
__device__ __forceinline__ float tanhf_(float x){
    float e = __expf(-2.f * x);
    return __fdividef(2.f, 1.f + e) - 1.f;
}

// ---------------- pack w_hh into [ld][k4][gate] float4 ----------------
__global__ void pack_whh(const float* __restrict__ w0f, const float* __restrict__ w0b,
                         const float* __restrict__ w1f, const float* __restrict__ w1b)
{
    int idx = blockIdx.x * 256 + threadIdx.x;        // 4*32*512 = 65536
    int g  = idx & 511;
    int k4 = (idx >> 9) & 31;
    int ld = idx >> 14;                              // layer*2+dir
    const float* W = (ld == 0) ? w0f : (ld == 1) ? w0b : (ld == 2) ? w1f : w1b;
    const float* p = W + g * HID + k4 * 4;
    g_whh[idx] = make_float4(p[0], p[1], p[2], p[3]);
}

// ---------------- embedding concat ----------------
__global__ void embed_kernel(const int* __restrict__ widx, const int* __restrict__ pidx,
                             const float* __restrict__ wemb, const float* __restrict__ temb)
{
    int bl = blockIdx.x;             // b*LEN + t
    int d  = threadIdx.x;            // 0..127
    int w = widx[bl];
    int p = pidx[bl];
    float v = (d < 100) ? wemb[w * 100 + d] : temb[p * 28 + (d - 100)];
    g_x[bl * EMB + d] = v;
}

// ---------------- generic tiled GEMM: C[m][n] = A[m][K]·W[n][wstride..K] + b1[n]+b2[n] ----------------
__global__ __launch_bounds__(256)
void gemm64(const float* __restrict__ A, const float* __restrict__ W,
            const float* __restrict__ b1, const float* __restrict__ b2,
            float* __restrict__ C, int N, int K, int wstride)
{
    __shared__ float As[16][68];
    __shared__ float Ws[16][68];
    int tid = threadIdx.x;
    int tx = tid & 15, ty = tid >> 4;
    int m0 = blockIdx.y * 64, n0 = blockIdx.x * 64;
    int lrow = tid >> 2;             // 0..63
    int lk   = (tid & 3) * 4;        // 0,4,8,12
    float acc[4][4];
    #pragma unroll
    for (int i = 0; i < 4; i++)
        #pragma unroll
        for (int j = 0; j < 4; j++) acc[i][j] = 0.f;

    for (int k0 = 0; k0 < K; k0 += 16){
        float4 av = *(const float4*)&A[(size_t)(m0 + lrow) * K + k0 + lk];
        int wn = n0 + lrow;
        float4 wv = make_float4(0.f,0.f,0.f,0.f);
        if (wn < N) wv = *(const float4*)&W[(size_t)wn * wstride + k0 + lk];
        As[lk+0][lrow] = av.x; As[lk+1][lrow] = av.y; As[lk+2][lrow] = av.z; As[lk+3][lrow] = av.w;
        Ws[lk+0][lrow] = wv.x; Ws[lk+1][lrow] = wv.y; Ws[lk+2][lrow] = wv.z; Ws[lk+3][lrow] = wv.w;
        __syncthreads();
        #pragma unroll
        for (int kk = 0; kk < 16; kk++){
            float4 a4 = *(const float4*)&As[kk][ty*4];
            float4 w4 = *(const float4*)&Ws[kk][tx*4];
            float av_[4] = {a4.x, a4.y, a4.z, a4.w};
            float wv_[4] = {w4.x, w4.y, w4.z, w4.w};
            #pragma unroll
            for (int i = 0; i < 4; i++)
                #pragma unroll
                for (int j = 0; j < 4; j++) acc[i][j] = fmaf(av_[i], wv_[j], acc[i][j]);
        }
        __syncthreads();
    }
    #pragma unroll
    for (int j = 0; j < 4; j++){
        int n = n0 + tx*4 + j;
        if (n >= N) continue;
        float bias = (b1 ? b1[n] : 0.f) + (b2 ? b2[n] : 0.f);
        #pragma unroll
        for (int i = 0; i < 4; i++){
            int m = m0 + ty*4 + i;
            C[(size_t)m * N + n] = acc[i][j] + bias;
        }
    }
}

// ---------------- LSTM recurrence: one CTA per (dir, batch) ----------------
// thread = gate (512). Weights: k 0..63 in regs (fp32), k 64..127 in smem.
__global__ __launch_bounds__(512, 1)
void lstm_kernel(const float* __restrict__ xp,    // [2][B][L][512]
                 const float4* __restrict__ whh,  // [2][32][512] for this layer
                 float* __restrict__ hcat)        // [B][L][256]
{
    extern __shared__ float4 w_sh[];              // [16][512] = 128KB
    __shared__ float4 h4_sh[32];
    __shared__ float  gates_sh[G4];

    int tid = threadIdx.x;
    int dir = blockIdx.x >> 4;
    int b   = blockIdx.x & 15;

    const float4* wd = whh + dir * 32 * G4;
    float4 wr[16];
    #pragma unroll
    for (int k4 = 0; k4 < 16; k4++) wr[k4] = wd[k4 * G4 + tid];
    #pragma unroll
    for (int k4 = 0; k4 < 16; k4++) w_sh[k4 * G4 + tid] = wd[(16 + k4) * G4 + tid];
    if (tid < 32) h4_sh[tid] = make_float4(0.f,0.f,0.f,0.f);
    float c = 0.f;
    const float* xpd = xp + ((size_t)(dir * BATCH + b)) * LEN * G4;
    bool is_g = (tid >= 256) && (tid < 384);
    __syncthreads();

    int t  = dir ? (LEN - 1) : 0;
    int dt = dir ? -1 : 1;
    float xg = xpd[t * G4 + tid];

    for (int s = 0; s < LEN; s++){
        float xg_next = (s < LEN - 1) ? xpd[(t + dt) * G4 + tid] : 0.f;
        float a0 = xg, a1 = 0.f, a2 = 0.f, a3 = 0.f;
        #pragma unroll
        for (int k4 = 0; k4 < 16; k4 += 4){
            float4 h0 = h4_sh[k4+0], h1 = h4_sh[k4+1], h2 = h4_sh[k4+2], h3 = h4_sh[k4+3];
            float4 w0 = wr[k4+0],    w1 = wr[k4+1],    w2 = wr[k4+2],    w3 = wr[k4+3];
            a0 += w0.x*h0.x + w0.y*h0.y + w0.z*h0.z + w0.w*h0.w;
            a1 += w1.x*h1.x + w1.y*h1.y + w1.z*h1.z + w1.w*h1.w;
            a2 += w2.x*h2.x + w2.y*h2.y + w2.z*h2.z + w2.w*h2.w;
            a3 += w3.x*h3.x + w3.y*h3.y + w3.z*h3.z + w3.w*h3.w;
        }
        #pragma unroll
        for (int k4 = 0; k4 < 16; k4 += 4){
            float4 h0 = h4_sh[16+k4+0], h1 = h4_sh[16+k4+1], h2 = h4_sh[16+k4+2], h3 = h4_sh[16+k4+3];
            float4 w0 = w_sh[(k4+0)*G4 + tid], w1 = w_sh[(k4+1)*G4 + tid];
            float4 w2 = w_sh[(k4+2)*G4 + tid], w3 = w_sh[(k4+3)*G4 + tid];
            a0 += w0.x*h0.x + w0.y*h0.y + w0.z*h0.z + w0.w*h0.w;
            a1 += w1.x*h1.x + w1.y*h1.y + w1.z*h1.z + w1.w*h1.w;
            a2 += w2.x*h2.x + w2.y*h2.y + w2.z*h2.z + w2.w*h2.w;
            a3 += w3.x*h3.x + w3.y*h3.y + w3.z*h3.z + w3.w*h3.w;
        }
        float acc = (a0 + a1) + (a2 + a3);
        gates_sh[tid] = is_g ? tanhf_(acc) : sigf(acc);
        __syncthreads();
        if (tid < HID){
            float gi = gates_sh[tid];
            float gf = gates_sh[HID + tid];
            float gg = gates_sh[2*HID + tid];
            float go = gates_sh[3*HID + tid];
            c = gf * c + gi * gg;
            float hv = go * tanhf_(c);
            ((float*)h4_sh)[tid] = hv;
            hcat[((size_t)b * LEN + t) * D2 + dir * HID + tid] = hv;
        }
        t += dt;
        xg = xg_next;
        __syncthreads();
    }
}

// ---------------- biaffine scorer ----------------
__global__ __launch_bounds__(128)
void scores_kernel(const float* __restrict__ w2, const float* __restrict__ b2,
                   float* __restrict__ out)
{
    int i  = blockIdx.x;      // 0..127
    int bq = blockIdx.y;      // 0..3 (4 batch per block)
    int j  = threadIdx.x;     // 0..127
    __shared__ float a_sh[4][100];
    __shared__ float w2_sh[100];
    if (j < 100){
        w2_sh[j] = w2[j];
        #pragma unroll
        for (int bi = 0; bi < 4; bi++)
            a_sh[bi][j] = g_a[((size_t)(bq*4+bi) * LEN + i) * 100 + j];
    }
    __syncthreads();
    float bb = b2[0];
    for (int bi = 0; bi < 4; bi++){
        int b = bq * 4 + bi;
        const float* bpr = g_bp + ((size_t)b * LEN + j) * 100;
        float acc = bb;
        #pragma unroll 4
        for (int k = 0; k < 100; k++)
            acc = fmaf(tanhf_(a_sh[bi][k] + bpr[k]), w2_sh[k], acc);
        out[(size_t)(i * LEN + j) * BATCH + b] = acc;
    }
}

// ---------------- launch ----------------
extern "C" void kernel_launch(void* const* d_in, const int* in_sizes, int n_in,
                              void* d_out, int out_size)
{
    const int*   widx = (const int*)  d_in[0];
    const int*   pidx = (const int*)  d_in[1];
    const float* wemb = (const float*)d_in[4];
    const float* temb = (const float*)d_in[5];
    const float* w_ih_l0f = (const float*)d_in[6];
    const float* w_hh_l0f = (const float*)d_in[7];
    const float* b_ih_l0f = (const float*)d_in[8];
    const float* b_hh_l0f = (const float*)d_in[9];
    const float* w_ih_l0b = (const float*)d_in[10];
    const float* w_hh_l0b = (const float*)d_in[11];
    const float* b_ih_l0b = (const float*)d_in[12];
    const float* b_hh_l0b = (const float*)d_in[13];
    const float* w_ih_l1f = (const float*)d_in[14];
    const float* w_hh_l1f = (const float*)d_in[15];
    const float* b_ih_l1f = (const float*)d_in[16];
    const float* b_hh_l1f = (const float*)d_in[17];
    const float* w_ih_l1b = (const float*)d_in[18];
    const float* w_hh_l1b = (const float*)d_in[19];
    const float* b_ih_l1b = (const float*)d_in[20];
    const float* b_hh_l1b = (const float*)d_in[21];
    const float* fc1_w = (const float*)d_in[22];
    const float* fc1_b = (const float*)d_in[23];
    const float* fc2_w = (const float*)d_in[24];
    const float* fc2_b = (const float*)d_in[25];
    float* out = (float*)d_out;

    // resolve scratch symbols
    float  *p_x, *p_xp, *p_h0, *p_h1, *p_a, *p_bp;
    float4 *p_whh;
    cudaGetSymbolAddress((void**)&p_x,   g_x);
    cudaGetSymbolAddress((void**)&p_xp,  g_xp);
    cudaGetSymbolAddress((void**)&p_h0,  g_h0);
    cudaGetSymbolAddress((void**)&p_h1,  g_h1);
    cudaGetSymbolAddress((void**)&p_a,   g_a);
    cudaGetSymbolAddress((void**)&p_bp,  g_bp);
    cudaGetSymbolAddress((void**)&p_whh, g_whh);

    cudaFuncSetAttribute(lstm_kernel, cudaFuncAttributeMaxDynamicSharedMemorySize, 131072);

    const int M = BATCH * LEN;   // 2048

    pack_whh<<<256, 256>>>(w_hh_l0f, w_hh_l0b, w_hh_l1f, w_hh_l1b);
    embed_kernel<<<M, 128>>>(widx, pidx, wemb, temb);

    // layer 0 input projections: xp[dir][b][t][512]
    gemm64<<<dim3(8, 32), 256>>>(p_x, w_ih_l0f, b_ih_l0f, b_hh_l0f, p_xp,             G4, EMB, EMB);
    gemm64<<<dim3(8, 32), 256>>>(p_x, w_ih_l0b, b_ih_l0b, b_hh_l0b, p_xp + M*G4,      G4, EMB, EMB);
    lstm_kernel<<<32, 512, 131072>>>(p_xp, p_whh, p_h0);

    // layer 1
    gemm64<<<dim3(8, 32), 256>>>(p_h0, w_ih_l1f, b_ih_l1f, b_hh_l1f, p_xp,            G4, D2, D2);
    gemm64<<<dim3(8, 32), 256>>>(p_h0, w_ih_l1b, b_ih_l1b, b_hh_l1b, p_xp + M*G4,     G4, D2, D2);
    lstm_kernel<<<32, 512, 131072>>>(p_xp, p_whh + 2*32*G4, p_h1);

    // fc1 split projections: a = h@wa^T ; bp = h@wb^T + fc1_b
    gemm64<<<dim3(2, 32), 256>>>(p_h1, fc1_w,        nullptr, nullptr, p_a,  100, D2, 512);
    gemm64<<<dim3(2, 32), 256>>>(p_h1, fc1_w + D2,   fc1_b,   nullptr, p_bp, 100, D2, 512);

    // scores
    scores_kernel<<<dim3(128, 4), 128>>>(fc2_w, fc2_b, out);
    (void)in_sizes; (void)n_in; (void)out_size;
}